// round 15
// baseline (speedup 1.0000x reference)
#include <cuda_runtime.h>
#include <cstdint>

// ============================================================================
// SpectralNetLoss:
//   2n·loss = Σ_ij W_ij(sq_i + sq_j) − 2 Σ_ij W_ij (y_i·y_j)
// ALL terms via one bf16 mma.sync m16n8k16 GEMM U = W × B̃,
//   B̃ = [Y | sq | 1 | 0…] (72 cols, 9 n8-fragments, rn-bf16 -> unbiased):
//   U[:,0..63] folded with Y -> dot;  U[:,64]=(W·sq)_i, U[:,65]=r_i -> term1.
// R15 = R14 math + staging, restructured 2 CTAs x 256 thr x 4 stages:
//   depth-3 prefetch (~2550cyc margin >> loaded DRAM latency) at the proven
//   32k chunk granule; R9-proven asymmetric 4/5 fragment warp split.
// ============================================================================

#define N_DIM     8192
#define KF        64
#define M_TILE    128
#define KCHUNK    32
#define KSPLIT    9
#define RS        40                        // R12-proven conflict-free stride

#define A_FLOATS  (M_TILE * RS)             // 5120
#define B_OFF     (A_FLOATS * 4)            // 20480
#define B_BYTES   4608                      // 2 kst x 9 nt x 32 lanes x 8B
#define STAGE_BYTES  (B_OFF + B_BYTES)      // 25088
#define STAGE_FLOATS (STAGE_BYTES / 4)      // 6272
#define N_STAGES  4
#define SMEM_BYTES   (N_STAGES * STAGE_BYTES)   // 100352 (x2 CTA = 200.7KB)

#define NCHUNK    (N_DIM / KCHUNK)          // 256

// B̃ packed per chunk c: [kst][nt][lane] uint2, lane = g*4+q:
//   .x = bf16x2( B̃[k0][n], B̃[k0+1][n] ),  .y = bf16x2( B̃[k0+8][n], B̃[k0+9][n] )
//   k0 = c*32 + kst*16 + 2q, n = nt*8+g.  nt=8 -> cols 64..71 = [sq|1|0…].
__device__ float g_Bp[(size_t)NCHUNK * B_BYTES / 4];
__device__ float g_sq[N_DIM];

// ---------------------------------------------------------------- helpers
__device__ __forceinline__ uint32_t smem_u32(const void* p) {
    uint32_t a;
    asm("{ .reg .u64 t; cvta.to.shared.u64 t, %1; cvt.u32.u64 %0, t; }"
        : "=r"(a) : "l"(p));
    return a;
}
__device__ __forceinline__ void cp_async16(uint32_t dst, const void* src) {
    asm volatile("cp.async.cg.shared.global [%0], [%1], 16;"
                 :: "r"(dst), "l"(src));
}
__device__ __forceinline__ void cp_commit() {
    asm volatile("cp.async.commit_group;" ::: "memory");
}
__device__ __forceinline__ void cp_wait3() {
    asm volatile("cp.async.wait_group 3;" ::: "memory");
}
__device__ __forceinline__ uint32_t bf16pair(float lo, float hi) {
    uint32_t r;   // hi -> upper 16 bits, lo -> lower 16 bits
    asm("cvt.rn.bf16x2.f32 %0, %1, %2;" : "=r"(r) : "f"(hi), "f"(lo));
    return r;
}
__device__ __forceinline__ void mma_bf16(float* c, const uint32_t* a,
                                         uint32_t b0, uint32_t b1) {
    asm volatile(
        "mma.sync.aligned.m16n8k16.row.col.f32.bf16.bf16.f32 "
        "{%0,%1,%2,%3}, {%4,%5,%6,%7}, {%8,%9}, {%0,%1,%2,%3};"
        : "+f"(c[0]), "+f"(c[1]), "+f"(c[2]), "+f"(c[3])
        : "r"(a[0]), "r"(a[1]), "r"(a[2]), "r"(a[3]), "r"(b0), "r"(b1));
}

// ---------------------------------------------------------------- fused prep
// Block b handles k-rows [b*32, b*32+32) = chunk b: sq + bf16 B̃ pack.
__global__ void spec_prep(const float* __restrict__ Y, float* __restrict__ out) {
    __shared__ float sY[32 * 72];           // [k][n], stride 72
    __shared__ float ssq[32];
    const int tid = threadIdx.x;
    const int b = blockIdx.x;
    const int k0g = b * 32;

    if (b == 0 && tid == 0) out[0] = 0.0f;

#pragma unroll
    for (int i = 0; i < 8; i++) {
        int idx = tid + i * 256;            // coalesced 32x64 load
        sY[(idx >> 6) * 72 + (idx & 63)] = Y[(size_t)k0g * KF + idx];
    }
    __syncthreads();

    {   // sq: 8 threads per row
        int r = tid >> 3, p = tid & 7;
        const float* row = sY + r * 72 + p * 8;
        float s = 0.0f;
#pragma unroll
        for (int c = 0; c < 8; c++) s += row[c] * row[c];
#pragma unroll
        for (int o = 4; o; o >>= 1) s += __shfl_xor_sync(0xffffffffu, s, o);
        if (p == 0) { ssq[r] = s; g_sq[k0g + r] = s; }
    }
    __syncthreads();

    // pack: 2 kst x 9 nt x 32 lanes = 576 uint2; coalesced 8B writes
#pragma unroll
    for (int i = 0; i < 3; i++) {
        int u = tid + i * 256;              // [kst][nt][lane]
        if (u >= 576) break;
        int lane = u & 31;
        int nt   = (u >> 5) % 9;
        int kst  = u / 288;
        int q = lane & 3, g = lane >> 2;
        int ka = kst * 16 + 2 * q;          // k rel. to chunk
        uint2 v;
        if (nt < 8) {
            int n = nt * 8 + g;
            v.x = bf16pair(sY[ka * 72 + n],       sY[(ka + 1) * 72 + n]);
            v.y = bf16pair(sY[(ka + 8) * 72 + n], sY[(ka + 9) * 72 + n]);
        } else if (g == 0) {                // col 64 = sq_k
            v.x = bf16pair(ssq[ka],     ssq[ka + 1]);
            v.y = bf16pair(ssq[ka + 8], ssq[ka + 9]);
        } else if (g == 1) {                // col 65 = ones
            v.x = bf16pair(1.0f, 1.0f);
            v.y = v.x;
        } else {                            // cols 66..71 = zeros
            v.x = 0u; v.y = 0u;
        }
        *(uint2*)((char*)g_Bp + (size_t)b * B_BYTES + u * 8) = v;
    }
}

// ---------------------------------------------------------------- loader
__device__ __forceinline__ void load_chunk(uint32_t sdst, const float* wp,
                                           const char* bp, int tid) {
#pragma unroll
    for (int u = 0; u < 4; u++) {
        int idx = tid + u * 256;                      // A: 128 rows x 8 float4
        int r = idx >> 3, sg = idx & 7;
        cp_async16(sdst + (uint32_t)(r * RS + sg * 4) * 4,
                   wp + (size_t)r * N_DIM + sg * 4);
    }
#pragma unroll
    for (int u = 0; u < 2; u++) {                     // B̃ pack: 288 float4
        int idx = tid + u * 256;
        if (idx < B_BYTES / 16)
            cp_async16(sdst + B_OFF + idx * 16, bp + idx * 16);
    }
}

// ---------------------------------------------------------------- main
__global__ void __launch_bounds__(256, 2)
spec_main(const float* __restrict__ W, const float* __restrict__ Y,
          float* __restrict__ out) {
    extern __shared__ float smem[];
    const uint32_t sb = smem_u32(smem);

    const int tid = threadIdx.x;
    const int w   = tid >> 5;
    const int lid = tid & 31;
    const int q   = lid & 3;
    const int g   = lid >> 2;
    const int mg  = w & 3;             // 32-row group (one per SMSP pair)
    const int ng  = w >> 2;            // 0: frags 0..3 | 1: frags 4..8

    const int bx    = blockIdx.x;
    const int mtile = bx & 63;
    const int ks    = bx >> 6;                              // 0..8
    const int m0    = mtile * M_TILE;
    const int c0    = (ks < 4) ? ks * 29 : 116 + (ks - 4) * 28;
    const int nch   = (ks < 4) ? 29 : 28;

    const float* wbase = W + (size_t)m0 * N_DIM + (size_t)c0 * KCHUNK;
    const char*  bbase = (const char*)g_Bp + (size_t)c0 * B_BYTES;

    float acc[2][5][4];                // ng0 uses [0..3]; ng1 [0..3]=frags4..7,
#pragma unroll                         // [4]=frag8 (cols 64..71)
    for (int mt = 0; mt < 2; mt++)
#pragma unroll
        for (int nt = 0; nt < 5; nt++)
#pragma unroll
            for (int v = 0; v < 4; v++) acc[mt][nt][v] = 0.0f;

    // prologue: chunks 0..2 in flight
#pragma unroll
    for (int p = 0; p < 3; p++) {
        load_chunk(sb + p * STAGE_BYTES, wbase + (size_t)p * KCHUNK,
                   bbase + (size_t)p * B_BYTES, tid);
        cp_commit();
    }

    for (int j = 0; j < nch; j++) {
        if (j + 3 < nch)
            load_chunk(sb + ((j + 3) & 3) * STAGE_BYTES,
                       wbase + (size_t)(j + 3) * KCHUNK,
                       bbase + (size_t)(j + 3) * B_BYTES, tid);
        cp_commit();                      // empty groups keep count aligned
        cp_wait3();                       // chunk j resident
        __syncthreads();

        const float* As = smem + (j & 3) * STAGE_FLOATS;
        const char*  Bb = (const char*)smem + (j & 3) * STAGE_BYTES + B_OFF +
                          lid * 8 + ng * 1024;

#pragma unroll
        for (int kst = 0; kst < 2; kst++) {
            const int k0 = kst * 16 + 2 * q;
            // A fragments: 4x conflict-free LDS.64 per mt (fp32 -> bf16x2)
            uint32_t a[2][4];
#pragma unroll
            for (int mt = 0; mt < 2; mt++) {
                const float* ap = As + (mg * 32 + mt * 16 + g) * RS + k0;
                float2 p00 = *(const float2*)ap;             // row g,   k +0,+1
                float2 p01 = *(const float2*)(ap + 8);       // row g,   k +8,+9
                float2 p10 = *(const float2*)(ap + 8 * RS);  // row g+8
                float2 p11 = *(const float2*)(ap + 8 * RS + 8);
                a[mt][0] = bf16pair(p00.x, p00.y);
                a[mt][1] = bf16pair(p10.x, p10.y);
                a[mt][2] = bf16pair(p01.x, p01.y);
                a[mt][3] = bf16pair(p11.x, p11.y);
            }
            // B̃ fragments: one conflict-free LDS.64 per nt
            const char* Bk = Bb + kst * (B_BYTES / 2);
#pragma unroll
            for (int nt = 0; nt < 4; nt++) {
                uint2 bb = *(const uint2*)(Bk + nt * 256);
                mma_bf16(acc[0][nt], a[0], bb.x, bb.y);
                mma_bf16(acc[1][nt], a[1], bb.x, bb.y);
            }
            if (ng) {                      // frag 8 (cols 64..71)
                uint2 bb = *(const uint2*)(Bk + 4 * 256);
                mma_bf16(acc[0][4], a[0], bb.x, bb.y);
                mma_bf16(acc[1][4], a[1], bb.x, bb.y);
            }
        }
        __syncthreads();                  // stage reads done before overwrite
    }

    // ------------- epilogue: fold U with Y + extra cols, reduce -------------
    const int rbase = m0 + mg * 32 + g;
    float sqi[2][2];
    sqi[0][0] = g_sq[rbase];      sqi[0][1] = g_sq[rbase + 8];
    sqi[1][0] = g_sq[rbase + 16]; sqi[1][1] = g_sq[rbase + 24];

    float dot = 0.0f, extra = 0.0f;
#pragma unroll
    for (int mt = 0; mt < 2; mt++) {
        const int r0 = m0 + mg * 32 + mt * 16 + g;
#pragma unroll
        for (int nt = 0; nt < 4; nt++) {
            const int cc = ng * 32 + nt * 8 + 2 * q;
            float2 y0 = *(const float2*)(Y + (size_t)r0 * KF + cc);
            float2 y1 = *(const float2*)(Y + (size_t)(r0 + 8) * KF + cc);
            dot += acc[mt][nt][0] * y0.x + acc[mt][nt][1] * y0.y +
                   acc[mt][nt][2] * y1.x + acc[mt][nt][3] * y1.y;
        }
        if (ng) {
            // q==0 lanes: c0 = col64 = (W·sq)_i, c1 = col65 = rowsum r_i
            // (rows g / g+8); q>=1 lanes hold zero columns -> exact 0.
            extra += acc[mt][4][0] + sqi[mt][0] * acc[mt][4][1] +
                     acc[mt][4][2] + sqi[mt][1] * acc[mt][4][3];
        }
    }
    float total = extra - 2.0f * dot;
#pragma unroll
    for (int o = 16; o; o >>= 1)
        total += __shfl_xor_sync(0xffffffffu, total, o);

    if (lid == 0) smem[w] = total;     // stages dead after final chunk barrier
    __syncthreads();
    if (tid == 0) {
        float s = 0.0f;
#pragma unroll
        for (int i = 0; i < 8; i++) s += smem[i];
        atomicAdd(out, s * (1.0f / (2.0f * (float)N_DIM)));
    }
}

// ---------------------------------------------------------------- launch
extern "C" void kernel_launch(void* const* d_in, const int* in_sizes, int n_in,
                              void* d_out, int out_size) {
    const float* W = (const float*)d_in[0];
    const float* Y = (const float*)d_in[1];
    float* out = (float*)d_out;

    cudaFuncSetAttribute(spec_main, cudaFuncAttributeMaxDynamicSharedMemorySize,
                         SMEM_BYTES);

    spec_prep<<<NCHUNK, 256>>>(Y, out);
    spec_main<<<64 * KSPLIT, 256, SMEM_BYTES>>>(W, Y, out);
}